// round 3
// baseline (speedup 1.0000x reference)
#include <cuda_runtime.h>
#include <float.h>
#include <math.h>

#define C_ 32
#define D_ 48
#define H_ 64
#define W_ 128
#define HW 8192           // H_*W_ == W_*H_ (same plane size transposed)
#define CDHW 12582912     // C_*D_*H_*W_
#define GDIR 1310720      // C_*5*HW

// ---- scratch (allocation-free rule: __device__ globals) ----
__device__ float g_xT[CDHW];          // x transposed [C,D,W,H]
__device__ float g_kT[2 * GDIR];      // k dirs 0,1 transposed [dir,C,5,W,H]
__device__ float g_aggH0[CDHW];       // H-forward scan output
__device__ float g_aggH1[CDHW];       // H-reverse scan output
__device__ float g_aggT0[CDHW];       // W-forward scan output (transposed layout)
__device__ float g_aggT1[CDHW];       // W-reverse scan output (transposed layout)
__device__ float g_y[CDHW];           // relu(bn1(max4)) -> conv input

// ===================== prep: tiled transposes ==============================
// blocks 0..12287: x planes (c*48+d), 8 tiles of 32x32 each
// blocks 12288..14847: k planes for dirs 0,1 (dir*160 + c*5+i), 8 tiles each
__global__ void __launch_bounds__(256) prep_transpose(const float* __restrict__ x,
                                                      const float* __restrict__ g)
{
    __shared__ float tile[32][33];
    const int b = blockIdx.x;
    const float* src;
    float* dst;
    if (b < 12288) {
        const int plane = b >> 3;
        src = x + plane * HW;
        dst = g_xT + plane * HW;
    } else {
        const int q = b - 12288;
        const int kplane = q >> 3;                 // 0..319
        const int dir = kplane / 160;              // 0 or 1
        const int rest = kplane - dir * 160;       // c*5+i
        src = g + dir * GDIR + rest * HW;
        dst = g_kT + kplane * HW;
    }
    const int tile_id = b & 7;
    const int h0 = (tile_id >> 2) * 32;
    const int w0 = (tile_id & 3) * 32;
    const int tx = threadIdx.x & 31;
    const int ty = threadIdx.x >> 5;
#pragma unroll
    for (int j = 0; j < 4; ++j) {
        const int r = ty + j * 8;
        tile[r][tx] = src[(h0 + r) * W_ + w0 + tx];
    }
    __syncthreads();
#pragma unroll
    for (int j = 0; j < 4; ++j) {
        const int r = ty + j * 8;
        dst[(w0 + r) * H_ + h0 + tx] = tile[tx][r];
    }
}

// ===================== register-fiber SGA scan =============================
__device__ __forceinline__ void pf48(const float* __restrict__ xp,
                                     const float* __restrict__ kp,
                                     int off, float X[48], float K[5])
{
#pragma unroll
    for (int d = 0; d < 48; ++d) X[d] = __ldg(xp + d * HW + off);
#pragma unroll
    for (int i = 0; i < 5; ++i)  K[i] = __ldg(kp + i * HW + off);
}

__device__ __forceinline__ void sga_body(float A[48], const float X[48], const float K[5],
                                         float* __restrict__ op, int off)
{
    const float s = fabsf(K[0]) + fabsf(K[1]) + fabsf(K[2]) + fabsf(K[3]) + fabsf(K[4]);
    const float inv = __fdividef(1.0f, fmaxf(s, 1e-12f));
    const float w0 = K[0] * inv, w1 = K[1] * inv, w2 = K[2] * inv,
                w3 = K[3] * inv, w4 = K[4] * inv;
    // max over prev A (explicit tree)
    float t[24];
#pragma unroll
    for (int i = 0; i < 24; ++i) t[i] = fmaxf(A[2 * i], A[2 * i + 1]);
#pragma unroll
    for (int i = 0; i < 12; ++i) t[i] = fmaxf(t[2 * i], t[2 * i + 1]);
#pragma unroll
    for (int i = 0; i < 6; ++i)  t[i] = fmaxf(t[2 * i], t[2 * i + 1]);
    const float m = fmaxf(fmaxf(fmaxf(t[0], t[1]), fmaxf(t[2], t[3])), fmaxf(t[4], t[5]));

    float prevm1 = 0.0f;
#pragma unroll
    for (int d = 0; d < 48; ++d) {
        const float nxt = (d < 47) ? A[d + 1] : 0.0f;
        float v = w0 * X[d];
        v = fmaf(w1, A[d], v);
        v = fmaf(w2, prevm1, v);
        v = fmaf(w3, nxt, v);
        v = fmaf(w4, m, v);
        prevm1 = A[d];
        A[d] = v;
        op[d * HW + off] = v;
    }
}

__device__ __forceinline__ void scan_warp(const float* __restrict__ xb,
                                          const float* __restrict__ kb,
                                          float* __restrict__ ob,
                                          int maj, int mn, int rev, int gw, int lane)
{
    const int wpc = mn >> 5;                 // warps per c (4 for H, 2 for W)
    const int c = gw / wpc;
    const int m = (gw - c * wpc) * 32 + lane;
    const float* xp = xb + c * 48 * HW + m;
    float* op = ob + c * 48 * HW + m;
    const float* kp = kb + c * 5 * HW + m;
    const int ds = rev ? -mn : mn;
    int off = rev ? (maj - 1) * mn : 0;

    float A[48];
#pragma unroll
    for (int d = 0; d < 48; ++d) {           // boundary pixel: A = C, stored raw
        const float v = __ldg(xp + d * HW + off);
        A[d] = v;
        op[d * HW + off] = v;
    }

    float X0[48], K0[5], X1[48], K1[5];
    int offc = off + ds;
    pf48(xp, kp, offc, X0, K0);
    const int nst = maj - 1;
    for (int s = 0; s < nst; s += 2) {
        const int offn = offc + ds;
        if (s + 1 < nst) pf48(xp, kp, offn, X1, K1);
        sga_body(A, X0, K0, op, offc);
        if (s + 1 < nst) {
            const int offn2 = offn + ds;
            if (s + 2 < nst) pf48(xp, kp, offn2, X0, K0);
            sga_body(A, X1, K1, op, offn);
            offc = offn2;
        }
    }
}

// 96 blocks x 128 threads; blocks select direction.
__global__ void __launch_bounds__(128) scan_kernel(const float* __restrict__ x,
                                                   const float* __restrict__ g)
{
    const int blk = blockIdx.x;
    const int warp = threadIdx.x >> 5;
    const int lane = threadIdx.x & 31;
    if (blk < 32) {
        scan_warp(x, g + 2 * GDIR, g_aggH0, H_, W_, 0, blk * 4 + warp, lane);
    } else if (blk < 64) {
        scan_warp(x, g + 3 * GDIR, g_aggH1, H_, W_, 1, (blk - 32) * 4 + warp, lane);
    } else if (blk < 80) {
        scan_warp(g_xT, g_kT, g_aggT0, W_, H_, 0, (blk - 64) * 4 + warp, lane);
    } else {
        scan_warp(g_xT, g_kT + GDIR, g_aggT1, W_, H_, 1, (blk - 80) * 4 + warp, lane);
    }
}

// ===================== combine: max4 + BN1 + ReLU ==========================
// 12288 blocks (plane * 8 tiles), in-smem transpose for the W buffers.
__global__ void __launch_bounds__(256) combine_kernel(const float* __restrict__ s1,
                                                      const float* __restrict__ b1)
{
    __shared__ float t0[32][33], t1[32][33];
    const int b = blockIdx.x;
    const int plane = b >> 3;                // c*48+d
    const int tile_id = b & 7;
    const int h0 = (tile_id >> 2) * 32;
    const int w0 = (tile_id & 3) * 32;
    const int c = plane / 48;
    const int tx = threadIdx.x & 31;
    const int ty = threadIdx.x >> 5;
    const int pb = plane * HW;
#pragma unroll
    for (int j = 0; j < 4; ++j) {
        const int r = ty + j * 8;
        const int ta = pb + (w0 + r) * H_ + h0 + tx;
        t0[r][tx] = g_aggT0[ta];
        t1[r][tx] = g_aggT1[ta];
    }
    __syncthreads();
    const float inv1 = s1[c] * rsqrtf(1.0f + 1e-5f);
    const float bb = b1[c];
#pragma unroll
    for (int j = 0; j < 4; ++j) {
        const int hh = ty + j * 8;
        const int na = pb + (h0 + hh) * W_ + w0 + tx;
        float v = fmaxf(fmaxf(g_aggH0[na], g_aggH1[na]),
                        fmaxf(t0[tx][hh], t1[tx][hh]));
        g_y[na] = fmaxf(v * inv1 + bb, 0.0f);
    }
}

// ===================== conv 3x3x3 + BN2 + residual + ReLU ==================
#define FMA2(d_, a_, b_, c_) \
    asm("fma.rn.f32x2 %0, %1, %2, %3;" : "=l"(d_) : "l"(a_), "l"(b_), "l"(c_))

__global__ void __launch_bounds__(128) conv_kernel(const float* __restrict__ wr,
                                                   const float* __restrict__ x,
                                                   const float* __restrict__ s2,
                                                   const float* __restrict__ b2,
                                                   float* __restrict__ out)
{
    __shared__ float insh[C_][136];          // padded rows: idx = w+1, [0..129] valid
    __shared__ float wsh[C_ * 96];           // [ci][kw][co]  (co contiguous!)

    const int d = blockIdx.x >> 6;
    const int h = blockIdx.x & 63;
    const int t = threadIdx.x;
    const int cg = t >> 4;                   // 0..7  -> co base 4*cg
    const int wg = t & 15;                   // 0..15 -> w base 8*wg

    unsigned long long acc0[8], acc1[8];     // packed (co, co+1) accumulators
#pragma unroll
    for (int i = 0; i < 8; ++i) { acc0[i] = 0ull; acc1[i] = 0ull; }

#pragma unroll
    for (int kd = 0; kd < 3; ++kd) {
        const int zd = d + kd - 1;
#pragma unroll
        for (int kh = 0; kh < 3; ++kh) {
            const int zh = h + kh - 1;
            const bool inb = (zd >= 0) && (zd < D_) && (zh >= 0) && (zh < H_);
            __syncthreads();
            if (inb) {
                // stage input rows: thread = (ci = t>>2, quarter = t&3)
                {
                    const int ci = t >> 2, sub = t & 3;
                    const float* gp = g_y + ((ci * D_ + zd) * H_ + zh) * W_;
#pragma unroll
                    for (int ii = 0; ii < 34; ++ii) {
                        const int idx = sub * 34 + ii;
                        const int wi = idx - 1;
                        insh[ci][idx] = (wi >= 0 && wi < W_) ? gp[wi] : 0.0f;
                    }
                }
                // stage weight slice: wsh[ci*96 + kw*32 + co]
                for (int j = t; j < C_ * 96; j += 128) {
                    const int ci = j / 96;
                    const int r = j - ci * 96;
                    const int kw = r >> 5;
                    const int co = r & 31;
                    wsh[j] = wr[(co * C_ + ci) * 27 + kd * 9 + kh * 3 + kw];
                }
            }
            __syncthreads();
            if (!inb) continue;

#pragma unroll 2
            for (int ci = 0; ci < C_; ++ci) {
                const float* ip = &insh[ci][wg * 8];
                const float4 iv0 = *(const float4*)(ip);
                const float4 iv1 = *(const float4*)(ip + 4);
                const float4 iv2 = *(const float4*)(ip + 8);
                const float iv[12] = {iv0.x, iv0.y, iv0.z, iv0.w,
                                      iv1.x, iv1.y, iv1.z, iv1.w,
                                      iv2.x, iv2.y, iv2.z, iv2.w};
                unsigned long long dup[10];
#pragma unroll
                for (int j = 0; j < 10; ++j) {
                    const unsigned r = __float_as_uint(iv[j]);
                    asm("mov.b64 %0, {%1, %1};" : "=l"(dup[j]) : "r"(r));
                }
#pragma unroll
                for (int kw = 0; kw < 3; ++kw) {
                    // wv.x = (w[co], w[co+1]), wv.y = (w[co+2], w[co+3]) for this kw
                    const ulonglong2 wv =
                        *(const ulonglong2*)&wsh[ci * 96 + kw * 32 + cg * 4];
#pragma unroll
                    for (int w = 0; w < 8; ++w) {
                        FMA2(acc0[w], dup[w + kw], wv.x, acc0[w]);
                        FMA2(acc1[w], dup[w + kw], wv.y, acc1[w]);
                    }
                }
            }
        }
    }

    // epilogue: unpack + BN2 + residual + ReLU
    const float rsq = rsqrtf(1.0f + 1e-5f);
#pragma unroll
    for (int cop = 0; cop < 2; ++cop) {
        const unsigned long long* acc = cop ? acc1 : acc0;
        const int ocA = cg * 4 + cop * 2;
        const int ocB = ocA + 1;
        const float invA = s2[ocA] * rsq, bbA = b2[ocA];
        const float invB = s2[ocB] * rsq, bbB = b2[ocB];
        const int offA = ((ocA * D_ + d) * H_ + h) * W_ + wg * 8;
        const int offB = ((ocB * D_ + d) * H_ + h) * W_ + wg * 8;
#pragma unroll
        for (int w = 0; w < 8; ++w) {
            unsigned lo, hi;
            asm("mov.b64 {%0, %1}, %2;" : "=r"(lo), "=r"(hi) : "l"(acc[w]));
            const float vA = __uint_as_float(lo) * invA + bbA + x[offA + w];
            const float vB = __uint_as_float(hi) * invB + bbB + x[offB + w];
            out[offA + w] = fmaxf(vA, 0.0f);
            out[offB + w] = fmaxf(vB, 0.0f);
        }
    }
}

// ===========================================================================
extern "C" void kernel_launch(void* const* d_in, const int* in_sizes, int n_in,
                              void* d_out, int out_size)
{
    const float* x  = (const float*)d_in[0];
    const float* g  = (const float*)d_in[1];
    const float* wr = (const float*)d_in[2];
    const float* s1 = (const float*)d_in[3];
    const float* b1 = (const float*)d_in[4];
    const float* s2 = (const float*)d_in[5];
    const float* b2 = (const float*)d_in[6];
    float* out = (float*)d_out;

    prep_transpose<<<14848, 256>>>(x, g);        // x -> xT, k(dir0,1) -> kT
    scan_kernel<<<96, 128>>>(x, g);              // all 4 directions concurrently
    combine_kernel<<<12288, 256>>>(s1, b1);      // max4 + BN1 + ReLU -> g_y
    conv_kernel<<<D_ * H_, 128>>>(wr, x, s2, b2, out);
}